// round 1
// baseline (speedup 1.0000x reference)
#include <cuda_runtime.h>

#define HH 4096
#define WW 4096
#define CC 3
#define R  8
#define OX 112          // output tile width
#define VX 128          // OX + 2R  (vsum columns)
#define OY 64           // output tile height
#define NT 512
#define VSTRIDE 129     // odd -> conflict-free across rows
#define ITSTRIDE 113    // odd -> conflict-free across rows
#define EPSF 1e-4f

#define VSUM_FLOATS (4 * OY * VSTRIDE)
#define IT_FLOATS   (OY * ITSTRIDE)
#define SMEM_BYTES  ((VSUM_FLOATS + IT_FLOATS) * 4)

__global__ __launch_bounds__(NT, 1)
void gf_kernel(const float* __restrict__ I, const float* __restrict__ P,
               float* __restrict__ Q)
{
    extern __shared__ float sm[];
    float* VS = sm;                  // [4][OY][VSTRIDE]
    float* IT = sm + VSUM_FLOATS;    // [OY][ITSTRIDE]  (i tile, then q tile)

    const int x0 = blockIdx.x * OX;
    const int y0 = blockIdx.y * OY;
    const long base = (long)blockIdx.z * HH * WW;
    const float* Ib = I + base;
    const float* Pb = P + base;
    const int tid = threadIdx.x;

    // ---------------- Phase 1: vertical sliding box sums ----------------
    {
        const int col     = tid & (VX - 1);   // 0..127
        const int quarter = tid >> 7;         // 0..3
        const int xg = x0 + col - R;
        const bool inX = (xg >= 0) && (xg < WW);
        const int ys = y0 + quarter * (OY / 4);   // first output row of quarter

        float si = 0.f, sp = 0.f, spi = 0.f, sii = 0.f;

        // warmup: rows [ys-R, ys+R]
        for (int dy = -R; dy <= R; ++dy) {
            int y = ys + dy;
            float iv = 0.f, pv = 0.f;
            if (inX && y >= 0 && y < HH) {
                iv = __ldg(Ib + (long)y * WW + xg);
                pv = __ldg(Pb + (long)y * WW + xg);
                int ry = y - y0;
                if (ry >= 0 && ry < OY && col >= R && col < R + OX)
                    IT[ry * ITSTRIDE + (col - R)] = iv;
            }
            si += iv; sp += pv; spi += pv * iv; sii += iv * iv;
        }
        int lr = quarter * (OY / 4);
        VS[(0 * OY + lr) * VSTRIDE + col] = si;
        VS[(1 * OY + lr) * VSTRIDE + col] = sp;
        VS[(2 * OY + lr) * VSTRIDE + col] = spi;
        VS[(3 * OY + lr) * VSTRIDE + col] = sii;

        for (int rr = 1; rr < OY / 4; ++rr) {
            int y  = ys + rr;
            int ya = y + R;        // entering row (>=1, so >=0 always)
            int yb = y - R - 1;    // leaving row  (< HH always)
            float iva = 0.f, pva = 0.f;
            if (inX && ya < HH) {
                iva = __ldg(Ib + (long)ya * WW + xg);
                pva = __ldg(Pb + (long)ya * WW + xg);
                int ry = ya - y0;
                if (ry >= 0 && ry < OY && col >= R && col < R + OX)
                    IT[ry * ITSTRIDE + (col - R)] = iva;
            }
            float ivb = 0.f, pvb = 0.f;
            if (inX && yb >= 0) {
                ivb = __ldg(Ib + (long)yb * WW + xg);
                pvb = __ldg(Pb + (long)yb * WW + xg);
            }
            si  += iva - ivb;
            sp  += pva - pvb;
            spi += pva * iva - pvb * ivb;
            sii += iva * iva - ivb * ivb;
            int l2 = lr + rr;
            VS[(0 * OY + l2) * VSTRIDE + col] = si;
            VS[(1 * OY + l2) * VSTRIDE + col] = sp;
            VS[(2 * OY + l2) * VSTRIDE + col] = spi;
            VS[(3 * OY + l2) * VSTRIDE + col] = sii;
        }
    }
    __syncthreads();

    // -------- Phase 2: horizontal sliding sums + guided-filter math ------
    {
        const int row = tid & (OY - 1);   // 0..63
        const int seg = tid >> 6;         // 0..7
        const int SEGW = OX / 8;          // 14
        const int xs = seg * SEGW;
        const int yg = y0 + row;

        int yl = yg - R; if (yl < 0) yl = 0;
        int yh = yg + R; if (yh > HH - 1) yh = HH - 1;
        const float ny = (float)(yh - yl + 1);

        const float* vs0 = VS + (0 * OY + row) * VSTRIDE;
        const float* vs1 = VS + (1 * OY + row) * VSTRIDE;
        const float* vs2 = VS + (2 * OY + row) * VSTRIDE;
        const float* vs3 = VS + (3 * OY + row) * VSTRIDE;

        float h0 = 0.f, h1 = 0.f, h2 = 0.f, h3 = 0.f;
        #pragma unroll
        for (int d = 0; d < 2 * R + 1; ++d) {
            h0 += vs0[xs + d];
            h1 += vs1[xs + d];
            h2 += vs2[xs + d];
            h3 += vs3[xs + d];
        }

        for (int j = 0; j < SEGW; ++j) {
            int xo = xs + j;
            int xg = x0 + xo;
            if (xg < WW) {
                int xl = xg - R; if (xl < 0) xl = 0;
                int xh = xg + R; if (xh > WW - 1) xh = WW - 1;
                float nx = (float)(xh - xl + 1);
                float invN = __fdividef(1.0f, ny * nx);
                float mi  = h0 * invN;
                float mp  = h1 * invN;
                float mpi = h2 * invN;
                float mii = h3 * invN;
                float cov_ip = mpi - mp * mi;
                float cov_ii = mii - mi * mi;
                float a = __fdividef(cov_ip, cov_ii + EPSF);
                float b = mp - a * mi;
                float iv = IT[row * ITSTRIDE + xo];
                float q = a * iv + b;
                q = fminf(fmaxf(q, 0.f), 1.f);
                IT[row * ITSTRIDE + xo] = q;   // in-place: i tile -> q tile
            }
            if (j < SEGW - 1) {
                h0 += vs0[xo + 2 * R + 1] - vs0[xo];
                h1 += vs1[xo + 2 * R + 1] - vs1[xo];
                h2 += vs2[xo + 2 * R + 1] - vs2[xo];
                h3 += vs3[xo + 2 * R + 1] - vs3[xo];
            }
        }
    }
    __syncthreads();

    // ---------------- Phase 3: coalesced store of q ----------------------
    {
        float* Qb = Q + base;
        for (int idx = tid; idx < OY * OX; idx += NT) {
            int row = idx / OX;
            int xo  = idx - row * OX;
            int xg  = x0 + xo;
            if (xg < WW)
                Qb[(long)(y0 + row) * WW + xg] = IT[row * ITSTRIDE + xo];
        }
    }
}

extern "C" void kernel_launch(void* const* d_in, const int* in_sizes, int n_in,
                              void* d_out, int out_size)
{
    const float* I = (const float*)d_in[0];
    const float* P = (const float*)d_in[1];
    float* Q = (float*)d_out;

    cudaFuncSetAttribute(gf_kernel,
                         cudaFuncAttributeMaxDynamicSharedMemorySize,
                         SMEM_BYTES);

    dim3 grid((WW + OX - 1) / OX, HH / OY, CC);
    gf_kernel<<<grid, NT, SMEM_BYTES>>>(I, P, Q);
}

// round 3
// speedup vs baseline: 2.6759x; 2.6759x over previous
#include <cuda_runtime.h>

#define HH 4096
#define WW 4096
#define CC 3
#define R  8
#define OX 112          // output tile width
#define VX 128          // OX + 2R  (vsum columns)
#define OY 64           // output tile height
#define QROWS 16        // output rows per thread-quarter
#define NROWS 32        // QROWS + 2R staged input rows
#define NT 512
#define VSTRIDE 129     // odd -> conflict-free across rows
#define ITSTRIDE 113    // odd -> conflict-free across rows
#define EPSF 1e-4f

#define VSUM_FLOATS (4 * OY * VSTRIDE)
#define IT_FLOATS   (OY * ITSTRIDE)
#define SMEM_BYTES  ((VSUM_FLOATS + IT_FLOATS) * 4)

__global__ __launch_bounds__(NT, 1)
void gf_kernel(const float* __restrict__ I, const float* __restrict__ P,
               float* __restrict__ Q)
{
    extern __shared__ float sm[];
    float* VS = sm;                  // [4][OY][VSTRIDE]
    float* IT = sm + VSUM_FLOATS;    // [OY][ITSTRIDE]  (i tile, then q tile)

    const int x0 = blockIdx.x * OX;
    const int y0 = blockIdx.y * OY;
    const long base = (long)blockIdx.z * HH * WW;
    const float* Ib = I + base;
    const float* Pb = P + base;
    const int tid = threadIdx.x;

    // ---------------- Phase 1: register-staged vertical box sums ----------
    {
        const int col     = tid & (VX - 1);   // 0..127
        const int quarter = tid >> 7;         // 0..3
        const int xg  = x0 + col - R;
        int xgc = xg; if (xgc < 0) xgc = 0; if (xgc > WW - 1) xgc = WW - 1;
        const float xmask = (xg >= 0 && xg < WW) ? 1.f : 0.f;

        const int ys     = y0 + quarter * QROWS;  // first output row
        const int yfirst = ys - R;                // first staged input row

        // --- batched loads: 64 independent LDGs, no branches -------------
        float ivr[NROWS], pvr[NROWS];
        #pragma unroll
        for (int k = 0; k < NROWS; ++k) {
            int y = yfirst + k;
            int yc = y; if (yc < 0) yc = 0; if (yc > HH - 1) yc = HH - 1;
            size_t off = (size_t)yc * WW + xgc;
            ivr[k] = __ldg(Ib + off);
            pvr[k] = __ldg(Pb + off);
        }
        // --- apply border masks (zero-extend) -----------------------------
        #pragma unroll
        for (int k = 0; k < NROWS; ++k) {
            int y = yfirst + k;
            float m = (y >= 0 && y < HH) ? xmask : 0.f;
            ivr[k] *= m;
            pvr[k] *= m;
        }

        // --- stash central i values for the epilogue ----------------------
        if (col >= R && col < R + OX) {
            #pragma unroll
            for (int k = 0; k < QROWS; ++k)
                IT[(quarter * QROWS + k) * ITSTRIDE + (col - R)] = ivr[k + R];
        }

        // --- warmup: rows [0, 2R] -----------------------------------------
        float si = 0.f, sp = 0.f, spi = 0.f, sii = 0.f;
        #pragma unroll
        for (int k = 0; k <= 2 * R; ++k) {
            si  += ivr[k];
            sp  += pvr[k];
            spi += pvr[k] * ivr[k];
            sii += ivr[k] * ivr[k];
        }
        const int lr = quarter * QROWS;
        VS[(0 * OY + lr) * VSTRIDE + col] = si;
        VS[(1 * OY + lr) * VSTRIDE + col] = sp;
        VS[(2 * OY + lr) * VSTRIDE + col] = spi;
        VS[(3 * OY + lr) * VSTRIDE + col] = sii;

        // --- register-only slides -----------------------------------------
        #pragma unroll
        for (int rr = 1; rr < QROWS; ++rr) {
            float ia = ivr[rr + 2 * R], pa = pvr[rr + 2 * R];
            float ib = ivr[rr - 1],     pb = pvr[rr - 1];
            si  += ia - ib;
            sp  += pa - pb;
            spi += pa * ia - pb * ib;
            sii += ia * ia - ib * ib;
            int l2 = lr + rr;
            VS[(0 * OY + l2) * VSTRIDE + col] = si;
            VS[(1 * OY + l2) * VSTRIDE + col] = sp;
            VS[(2 * OY + l2) * VSTRIDE + col] = spi;
            VS[(3 * OY + l2) * VSTRIDE + col] = sii;
        }
    }
    __syncthreads();

    // -------- Phase 2: horizontal sliding sums + guided-filter math ------
    {
        const int row = tid & (OY - 1);   // 0..63
        const int seg = tid >> 6;         // 0..7
        const int SEGW = OX / 8;          // 14
        const int xs = seg * SEGW;
        const int yg = y0 + row;

        int yl = yg - R; if (yl < 0) yl = 0;
        int yh = yg + R; if (yh > HH - 1) yh = HH - 1;
        const float ny = (float)(yh - yl + 1);

        const float* vs0 = VS + (0 * OY + row) * VSTRIDE;
        const float* vs1 = VS + (1 * OY + row) * VSTRIDE;
        const float* vs2 = VS + (2 * OY + row) * VSTRIDE;
        const float* vs3 = VS + (3 * OY + row) * VSTRIDE;

        float h0 = 0.f, h1 = 0.f, h2 = 0.f, h3 = 0.f;
        #pragma unroll
        for (int d = 0; d < 2 * R + 1; ++d) {
            h0 += vs0[xs + d];
            h1 += vs1[xs + d];
            h2 += vs2[xs + d];
            h3 += vs3[xs + d];
        }

        #pragma unroll
        for (int j = 0; j < SEGW; ++j) {
            int xo = xs + j;
            int xg = x0 + xo;
            if (xg < WW) {
                int xl = xg - R; if (xl < 0) xl = 0;
                int xh = xg + R; if (xh > WW - 1) xh = WW - 1;
                float nx = (float)(xh - xl + 1);
                float invN = __fdividef(1.0f, ny * nx);
                float mi  = h0 * invN;
                float mp  = h1 * invN;
                float mpi = h2 * invN;
                float mii = h3 * invN;
                float cov_ip = mpi - mp * mi;
                float cov_ii = mii - mi * mi;
                float a = __fdividef(cov_ip, cov_ii + EPSF);
                float b = mp - a * mi;
                float iv = IT[row * ITSTRIDE + xo];
                float q = a * iv + b;
                q = fminf(fmaxf(q, 0.f), 1.f);
                IT[row * ITSTRIDE + xo] = q;   // in-place: i tile -> q tile
            }
            if (j < SEGW - 1) {
                h0 += vs0[xo + 2 * R + 1] - vs0[xo];
                h1 += vs1[xo + 2 * R + 1] - vs1[xo];
                h2 += vs2[xo + 2 * R + 1] - vs2[xo];
                h3 += vs3[xo + 2 * R + 1] - vs3[xo];
            }
        }
    }
    __syncthreads();

    // ---------------- Phase 3: coalesced store of q ----------------------
    {
        float* Qb = Q + base;
        for (int idx = tid; idx < OY * OX; idx += NT) {
            int row = idx / OX;
            int xo  = idx - row * OX;
            int xg  = x0 + xo;
            if (xg < WW)
                Qb[(long)(y0 + row) * WW + xg] = IT[row * ITSTRIDE + xo];
        }
    }
}

extern "C" void kernel_launch(void* const* d_in, const int* in_sizes, int n_in,
                              void* d_out, int out_size)
{
    const float* I = (const float*)d_in[0];
    const float* P = (const float*)d_in[1];
    float* Q = (float*)d_out;

    cudaFuncSetAttribute(gf_kernel,
                         cudaFuncAttributeMaxDynamicSharedMemorySize,
                         SMEM_BYTES);

    dim3 grid((WW + OX - 1) / OX, HH / OY, CC);
    gf_kernel<<<grid, NT, SMEM_BYTES>>>(I, P, Q);
}

// round 4
// speedup vs baseline: 3.2172x; 1.2023x over previous
#include <cuda_runtime.h>

#define HH 4096
#define WW 4096
#define CC 3
#define R  8
#define OX 112          // output tile width
#define VX 128          // OX + 2R  (vsum columns)
#define OY 64           // output tile height
#define QROWS 16        // output rows per thread-quarter
#define NROWS 32        // QROWS + 2R staged input rows
#define NT 512
#define V4STRIDE 129    // float4 per VS row (odd -> conflict-free)
#define ITSTRIDE 113    // odd -> conflict-free across rows
#define EPSF 1e-4f

#define VS_FLOATS (OY * V4STRIDE * 4)
#define IT_FLOATS (OY * ITSTRIDE)
#define SMEM_BYTES ((VS_FLOATS + IT_FLOATS) * 4)

__global__ __launch_bounds__(NT, 1)
void gf_kernel(const float* __restrict__ I, const float* __restrict__ P,
               float* __restrict__ Q)
{
    extern __shared__ float sm[];
    float* VSf = sm;                 // [OY][V4STRIDE] of float4 {si,sp,spi,sii}
    float* IT  = sm + VS_FLOATS;     // [OY][ITSTRIDE] (i tile, then q tile)
    float4* VS = (float4*)VSf;

    const int x0 = blockIdx.x * OX;
    const int y0 = blockIdx.y * OY;
    const long base = (long)blockIdx.z * HH * WW;
    const float* Ib = I + base;
    const float* Pb = P + base;
    const int tid = threadIdx.x;

    const bool interior = (x0 >= R) && (x0 + OX + R <= WW) &&
                          (y0 >= R) && (y0 + OY + R <= HH);

    // ---------------- Phase 1: register-staged vertical box sums ----------
    {
        const int col     = tid & (VX - 1);   // 0..127
        const int quarter = tid >> 7;         // 0..3
        const int ys      = y0 + quarter * QROWS;
        const int yfirst  = ys - R;

        float ivr[NROWS], pvr[NROWS];

        if (interior) {
            const float* pI = Ib + (size_t)yfirst * WW + (x0 + col - R);
            const float* pP = Pb + (size_t)yfirst * WW + (x0 + col - R);
            #pragma unroll
            for (int k = 0; k < NROWS; ++k) {
                ivr[k] = __ldg(pI + (size_t)k * WW);
                pvr[k] = __ldg(pP + (size_t)k * WW);
            }
        } else {
            const int xg = x0 + col - R;
            int xgc = xg; if (xgc < 0) xgc = 0; if (xgc > WW - 1) xgc = WW - 1;
            const float xmask = (xg >= 0 && xg < WW) ? 1.f : 0.f;
            #pragma unroll
            for (int k = 0; k < NROWS; ++k) {
                int y = yfirst + k;
                int yc = y; if (yc < 0) yc = 0; if (yc > HH - 1) yc = HH - 1;
                size_t off = (size_t)yc * WW + xgc;
                ivr[k] = __ldg(Ib + off);
                pvr[k] = __ldg(Pb + off);
            }
            #pragma unroll
            for (int k = 0; k < NROWS; ++k) {
                int y = yfirst + k;
                float m = (y >= 0 && y < HH) ? xmask : 0.f;
                ivr[k] *= m;
                pvr[k] *= m;
            }
        }

        // stash central i values for the epilogue
        if (col >= R && col < R + OX) {
            #pragma unroll
            for (int k = 0; k < QROWS; ++k)
                IT[(quarter * QROWS + k) * ITSTRIDE + (col - R)] = ivr[k + R];
        }

        // warmup: rows [0, 2R]
        float si = 0.f, sp = 0.f, spi = 0.f, sii = 0.f;
        #pragma unroll
        for (int k = 0; k <= 2 * R; ++k) {
            si  += ivr[k];
            sp  += pvr[k];
            spi += pvr[k] * ivr[k];
            sii += ivr[k] * ivr[k];
        }
        float4* vp = VS + (quarter * QROWS) * V4STRIDE + col;
        *vp = make_float4(si, sp, spi, sii);

        // register-only slides
        #pragma unroll
        for (int rr = 1; rr < QROWS; ++rr) {
            float ia = ivr[rr + 2 * R], pa = pvr[rr + 2 * R];
            float ib = ivr[rr - 1],     pb = pvr[rr - 1];
            si  += ia - ib;
            sp  += pa - pb;
            spi += pa * ia - pb * ib;
            sii += ia * ia - ib * ib;
            vp += V4STRIDE;
            *vp = make_float4(si, sp, spi, sii);
        }
    }
    __syncthreads();

    // -------- Phase 2: horizontal sliding sums + guided-filter math ------
    {
        const int row = tid & (OY - 1);   // 0..63
        const int seg = tid >> 6;         // 0..7
        const int SEGW = OX / 8;          // 14
        const int xs = seg * SEGW;
        const float4* vrow = VS + row * V4STRIDE;
        float* itrow = IT + row * ITSTRIDE;

        float h0 = 0.f, h1 = 0.f, h2 = 0.f, h3 = 0.f;
        #pragma unroll
        for (int d = 0; d < 2 * R + 1; ++d) {
            float4 t = vrow[xs + d];
            h0 += t.x; h1 += t.y; h2 += t.z; h3 += t.w;
        }

        if (interior) {
            const float invN = 1.0f / ((2 * R + 1) * (2 * R + 1));
            #pragma unroll
            for (int j = 0; j < SEGW; ++j) {
                int xo = xs + j;
                float mi  = h0 * invN;
                float mp  = h1 * invN;
                float mpi = h2 * invN;
                float mii = h3 * invN;
                float cov_ip = mpi - mp * mi;
                float cov_ii = mii - mi * mi;
                float a = __fdividef(cov_ip, cov_ii + EPSF);
                float b = mp - a * mi;
                float iv = itrow[xo];
                float q = fminf(fmaxf(a * iv + b, 0.f), 1.f);
                itrow[xo] = q;
                if (j < SEGW - 1) {
                    float4 ta = vrow[xo + 2 * R + 1];
                    float4 tb = vrow[xo];
                    h0 += ta.x - tb.x;
                    h1 += ta.y - tb.y;
                    h2 += ta.z - tb.z;
                    h3 += ta.w - tb.w;
                }
            }
        } else {
            const int yg = y0 + row;
            int yl = yg - R; if (yl < 0) yl = 0;
            int yh = yg + R; if (yh > HH - 1) yh = HH - 1;
            const float ny = (float)(yh - yl + 1);
            #pragma unroll
            for (int j = 0; j < SEGW; ++j) {
                int xo = xs + j;
                int xg = x0 + xo;
                if (xg < WW) {
                    int xl = xg - R; if (xl < 0) xl = 0;
                    int xh = xg + R; if (xh > WW - 1) xh = WW - 1;
                    float nx = (float)(xh - xl + 1);
                    float invN = __fdividef(1.0f, ny * nx);
                    float mi  = h0 * invN;
                    float mp  = h1 * invN;
                    float mpi = h2 * invN;
                    float mii = h3 * invN;
                    float cov_ip = mpi - mp * mi;
                    float cov_ii = mii - mi * mi;
                    float a = __fdividef(cov_ip, cov_ii + EPSF);
                    float b = mp - a * mi;
                    float iv = itrow[xo];
                    float q = fminf(fmaxf(a * iv + b, 0.f), 1.f);
                    itrow[xo] = q;
                }
                if (j < SEGW - 1) {
                    float4 ta = vrow[xo + 2 * R + 1];
                    float4 tb = vrow[xo];
                    h0 += ta.x - tb.x;
                    h1 += ta.y - tb.y;
                    h2 += ta.z - tb.z;
                    h3 += ta.w - tb.w;
                }
            }
        }
    }
    __syncthreads();

    // ---------------- Phase 3: coalesced store of q ----------------------
    {
        float* Qb = Q + base + (size_t)y0 * WW + x0;
        int row = tid / OX;
        int xo  = tid - row * OX;
        if (interior || x0 + OX <= WW) {
            #pragma unroll
            for (int it = 0; it < (OY * OX) / NT; ++it) {   // 14 iters, exact
                Qb[(size_t)row * WW + xo] = IT[row * ITSTRIDE + xo];
                xo += NT - 4 * OX;     // 512 = 4*112 + 64
                row += 4;
                if (xo >= OX) { xo -= OX; row += 1; }
            }
        } else {
            #pragma unroll
            for (int it = 0; it < (OY * OX) / NT; ++it) {
                if (x0 + xo < WW)
                    Qb[(size_t)row * WW + xo] = IT[row * ITSTRIDE + xo];
                xo += NT - 4 * OX;
                row += 4;
                if (xo >= OX) { xo -= OX; row += 1; }
            }
        }
    }
}

extern "C" void kernel_launch(void* const* d_in, const int* in_sizes, int n_in,
                              void* d_out, int out_size)
{
    const float* I = (const float*)d_in[0];
    const float* P = (const float*)d_in[1];
    float* Q = (float*)d_out;

    cudaFuncSetAttribute(gf_kernel,
                         cudaFuncAttributeMaxDynamicSharedMemorySize,
                         SMEM_BYTES);

    dim3 grid((WW + OX - 1) / OX, HH / OY, CC);
    gf_kernel<<<grid, NT, SMEM_BYTES>>>(I, P, Q);
}

// round 5
// speedup vs baseline: 4.0306x; 1.2528x over previous
#include <cuda_runtime.h>

#define HH 4096
#define WW 4096
#define CC 3
#define R  8
#define OX 112          // output tile width
#define VX 128          // OX + 2R  (vsum columns)
#define OY 32           // output tile height
#define QROWS 16        // output rows per thread-group
#define NROWS 32        // QROWS + 2R staged input rows
#define NT 256
#define V4STRIDE 129    // float4 per VS row (odd -> conflict-free)
#define ITSTRIDE 113    // odd -> conflict-free across rows
#define EPSF 1e-4f

#define VS_FLOATS (OY * V4STRIDE * 4)
#define IT_FLOATS (OY * ITSTRIDE)
#define SMEM_BYTES ((VS_FLOATS + IT_FLOATS) * 4)

__global__ __launch_bounds__(NT, 2)
void gf_kernel(const float* __restrict__ I, const float* __restrict__ P,
               float* __restrict__ Q)
{
    extern __shared__ float sm[];
    float* VSf = sm;                 // [OY][V4STRIDE] of float4 {si,sp,spi,sii}
    float* IT  = sm + VS_FLOATS;     // [OY][ITSTRIDE] (i tile, then q tile)
    float4* VS = (float4*)VSf;

    const int x0 = blockIdx.x * OX;
    const int y0 = blockIdx.y * OY;
    const long base = (long)blockIdx.z * HH * WW;
    const float* Ib = I + base;
    const float* Pb = P + base;
    const int tid = threadIdx.x;

    const bool interior = (x0 >= R) && (x0 + OX + R <= WW) &&
                          (y0 >= R) && (y0 + OY + R <= HH);

    // ---------------- Phase 1: register-staged vertical box sums ----------
    {
        const int col   = tid & (VX - 1);   // 0..127
        const int group = tid >> 7;         // 0..1
        const int ys     = y0 + group * QROWS;
        const int yfirst = ys - R;

        float ivr[NROWS], pvr[NROWS];

        if (interior) {
            const float* pI = Ib + (size_t)yfirst * WW + (x0 + col - R);
            const float* pP = Pb + (size_t)yfirst * WW + (x0 + col - R);
            #pragma unroll
            for (int k = 0; k < NROWS; ++k) {
                ivr[k] = __ldg(pI + (size_t)k * WW);
                pvr[k] = __ldg(pP + (size_t)k * WW);
            }
        } else {
            const int xg = x0 + col - R;
            int xgc = xg; if (xgc < 0) xgc = 0; if (xgc > WW - 1) xgc = WW - 1;
            const float xmask = (xg >= 0 && xg < WW) ? 1.f : 0.f;
            #pragma unroll
            for (int k = 0; k < NROWS; ++k) {
                int y = yfirst + k;
                int yc = y; if (yc < 0) yc = 0; if (yc > HH - 1) yc = HH - 1;
                size_t off = (size_t)yc * WW + xgc;
                ivr[k] = __ldg(Ib + off);
                pvr[k] = __ldg(Pb + off);
            }
            #pragma unroll
            for (int k = 0; k < NROWS; ++k) {
                int y = yfirst + k;
                float m = (y >= 0 && y < HH) ? xmask : 0.f;
                ivr[k] *= m;
                pvr[k] *= m;
            }
        }

        // stash central i values for the epilogue
        if (col >= R && col < R + OX) {
            #pragma unroll
            for (int k = 0; k < QROWS; ++k)
                IT[(group * QROWS + k) * ITSTRIDE + (col - R)] = ivr[k + R];
        }

        // warmup: rows [0, 2R]
        float si = 0.f, sp = 0.f, spi = 0.f, sii = 0.f;
        #pragma unroll
        for (int k = 0; k <= 2 * R; ++k) {
            si  += ivr[k];
            sp  += pvr[k];
            spi += pvr[k] * ivr[k];
            sii += ivr[k] * ivr[k];
        }
        float4* vp = VS + (group * QROWS) * V4STRIDE + col;
        *vp = make_float4(si, sp, spi, sii);

        // register-only slides
        #pragma unroll
        for (int rr = 1; rr < QROWS; ++rr) {
            float ia = ivr[rr + 2 * R], pa = pvr[rr + 2 * R];
            float ib = ivr[rr - 1],     pb = pvr[rr - 1];
            si  += ia - ib;
            sp  += pa - pb;
            spi += pa * ia - pb * ib;
            sii += ia * ia - ib * ib;
            vp += V4STRIDE;
            *vp = make_float4(si, sp, spi, sii);
        }
    }
    __syncthreads();

    // -------- Phase 2: horizontal sliding sums + guided-filter math ------
    {
        const int row = tid & (OY - 1);   // 0..31
        const int seg = tid >> 5;         // 0..7
        const int SEGW = OX / 8;          // 14
        const int xs = seg * SEGW;
        const float4* vrow = VS + row * V4STRIDE;
        float* itrow = IT + row * ITSTRIDE;

        float h0 = 0.f, h1 = 0.f, h2 = 0.f, h3 = 0.f;
        #pragma unroll
        for (int d = 0; d < 2 * R + 1; ++d) {
            float4 t = vrow[xs + d];
            h0 += t.x; h1 += t.y; h2 += t.z; h3 += t.w;
        }

        if (interior) {
            const float invN = 1.0f / ((2 * R + 1) * (2 * R + 1));
            #pragma unroll
            for (int j = 0; j < SEGW; ++j) {
                int xo = xs + j;
                float mi  = h0 * invN;
                float mp  = h1 * invN;
                float mpi = h2 * invN;
                float mii = h3 * invN;
                float cov_ip = mpi - mp * mi;
                float cov_ii = mii - mi * mi;
                float a = __fdividef(cov_ip, cov_ii + EPSF);
                float b = mp - a * mi;
                float iv = itrow[xo];
                float q = fminf(fmaxf(a * iv + b, 0.f), 1.f);
                itrow[xo] = q;
                if (j < SEGW - 1) {
                    float4 ta = vrow[xo + 2 * R + 1];
                    float4 tb = vrow[xo];
                    h0 += ta.x - tb.x;
                    h1 += ta.y - tb.y;
                    h2 += ta.z - tb.z;
                    h3 += ta.w - tb.w;
                }
            }
        } else {
            const int yg = y0 + row;
            int yl = yg - R; if (yl < 0) yl = 0;
            int yh = yg + R; if (yh > HH - 1) yh = HH - 1;
            const float ny = (float)(yh - yl + 1);
            #pragma unroll
            for (int j = 0; j < SEGW; ++j) {
                int xo = xs + j;
                int xg = x0 + xo;
                if (xg < WW) {
                    int xl = xg - R; if (xl < 0) xl = 0;
                    int xh = xg + R; if (xh > WW - 1) xh = WW - 1;
                    float nx = (float)(xh - xl + 1);
                    float invN = __fdividef(1.0f, ny * nx);
                    float mi  = h0 * invN;
                    float mp  = h1 * invN;
                    float mpi = h2 * invN;
                    float mii = h3 * invN;
                    float cov_ip = mpi - mp * mi;
                    float cov_ii = mii - mi * mi;
                    float a = __fdividef(cov_ip, cov_ii + EPSF);
                    float b = mp - a * mi;
                    float iv = itrow[xo];
                    float q = fminf(fmaxf(a * iv + b, 0.f), 1.f);
                    itrow[xo] = q;
                }
                if (j < SEGW - 1) {
                    float4 ta = vrow[xo + 2 * R + 1];
                    float4 tb = vrow[xo];
                    h0 += ta.x - tb.x;
                    h1 += ta.y - tb.y;
                    h2 += ta.z - tb.z;
                    h3 += ta.w - tb.w;
                }
            }
        }
    }
    __syncthreads();

    // ---------------- Phase 3: coalesced store of q ----------------------
    {
        float* Qb = Q + base + (size_t)y0 * WW + x0;
        int row = tid / OX;
        int xo  = tid - row * OX;
        if (x0 + OX <= WW) {
            #pragma unroll
            for (int it = 0; it < (OY * OX) / NT; ++it) {   // 14 iters, exact
                Qb[(size_t)row * WW + xo] = IT[row * ITSTRIDE + xo];
                xo += NT - 2 * OX;     // 256 = 2*112 + 32
                row += 2;
                if (xo >= OX) { xo -= OX; row += 1; }
            }
        } else {
            #pragma unroll
            for (int it = 0; it < (OY * OX) / NT; ++it) {
                if (x0 + xo < WW)
                    Qb[(size_t)row * WW + xo] = IT[row * ITSTRIDE + xo];
                xo += NT - 2 * OX;
                row += 2;
                if (xo >= OX) { xo -= OX; row += 1; }
            }
        }
    }
}

extern "C" void kernel_launch(void* const* d_in, const int* in_sizes, int n_in,
                              void* d_out, int out_size)
{
    const float* I = (const float*)d_in[0];
    const float* P = (const float*)d_in[1];
    float* Q = (float*)d_out;

    cudaFuncSetAttribute(gf_kernel,
                         cudaFuncAttributeMaxDynamicSharedMemorySize,
                         SMEM_BYTES);

    dim3 grid((WW + OX - 1) / OX, HH / OY, CC);
    gf_kernel<<<grid, NT, SMEM_BYTES>>>(I, P, Q);
}

// round 6
// speedup vs baseline: 4.0664x; 1.0089x over previous
#include <cuda_runtime.h>

#define HH 4096
#define WW 4096
#define CC 3
#define R  8
#define OX 112          // output tile width
#define VX 128          // OX + 2R  (vsum columns)
#define OY 32           // output tile height
#define QROWS 16        // output rows per thread-group
#define NROWS 32        // QROWS + 2R staged input rows
#define NT 256
#define SEGW 14         // OX / 8
#define V4STRIDE 129    // float4 per VS row (odd -> conflict-free)
#define ITSTRIDE 113    // odd -> conflict-free across rows
#define EPSF 1e-4f

#define VS_FLOATS (OY * V4STRIDE * 4)
#define IT_FLOATS (OY * ITSTRIDE)
#define SMEM_BYTES ((VS_FLOATS + IT_FLOATS) * 4)

__global__ __launch_bounds__(NT, 2)
void gf_kernel(const float* __restrict__ I, const float* __restrict__ P,
               float* __restrict__ Q)
{
    extern __shared__ float sm[];
    float* VSf = sm;                 // [OY][V4STRIDE] of float4 {si,sp,spi,sii}
    float* IT  = sm + VS_FLOATS;     // [OY][ITSTRIDE] (i tile, then q tile)
    float4* VS = (float4*)VSf;

    const int x0 = blockIdx.x * OX;
    const int y0 = blockIdx.y * OY;
    const long base = (long)blockIdx.z * HH * WW;
    const float* Ib = I + base;
    const float* Pb = P + base;
    const int tid = threadIdx.x;

    const bool interior = (x0 >= R) && (x0 + OX + R <= WW) &&
                          (y0 >= R) && (y0 + OY + R <= HH);

    // ---------------- Phase 1: register-staged vertical box sums ----------
    {
        const int col   = tid & (VX - 1);   // 0..127
        const int group = tid >> 7;         // 0..1
        const int ys     = y0 + group * QROWS;
        const int yfirst = ys - R;

        float ivr[NROWS], pvr[NROWS];

        if (interior) {
            const float* pI = Ib + (size_t)yfirst * WW + (x0 + col - R);
            const float* pP = Pb + (size_t)yfirst * WW + (x0 + col - R);
            #pragma unroll
            for (int k = 0; k < NROWS; ++k) {
                ivr[k] = __ldg(pI + (size_t)k * WW);
                pvr[k] = __ldg(pP + (size_t)k * WW);
            }
        } else {
            const int xg = x0 + col - R;
            int xgc = xg; if (xgc < 0) xgc = 0; if (xgc > WW - 1) xgc = WW - 1;
            const float xmask = (xg >= 0 && xg < WW) ? 1.f : 0.f;
            #pragma unroll
            for (int k = 0; k < NROWS; ++k) {
                int y = yfirst + k;
                int yc = y; if (yc < 0) yc = 0; if (yc > HH - 1) yc = HH - 1;
                size_t off = (size_t)yc * WW + xgc;
                ivr[k] = __ldg(Ib + off);
                pvr[k] = __ldg(Pb + off);
            }
            #pragma unroll
            for (int k = 0; k < NROWS; ++k) {
                int y = yfirst + k;
                float m = (y >= 0 && y < HH) ? xmask : 0.f;
                ivr[k] *= m;
                pvr[k] *= m;
            }
        }

        // stash central i values for the epilogue
        if (col >= R && col < R + OX) {
            #pragma unroll
            for (int k = 0; k < QROWS; ++k)
                IT[(group * QROWS + k) * ITSTRIDE + (col - R)] = ivr[k + R];
        }

        // warmup: rows [0, 2R]
        float si = 0.f, sp = 0.f, spi = 0.f, sii = 0.f;
        #pragma unroll
        for (int k = 0; k <= 2 * R; ++k) {
            si  += ivr[k];
            sp  += pvr[k];
            spi += pvr[k] * ivr[k];
            sii += ivr[k] * ivr[k];
        }
        float4* vp = VS + (group * QROWS) * V4STRIDE + col;
        *vp = make_float4(si, sp, spi, sii);

        // register-only slides
        #pragma unroll
        for (int rr = 1; rr < QROWS; ++rr) {
            float ia = ivr[rr + 2 * R], pa = pvr[rr + 2 * R];
            float ib = ivr[rr - 1],     pb = pvr[rr - 1];
            si  += ia - ib;
            sp  += pa - pb;
            spi += pa * ia - pb * ib;
            sii += ia * ia - ib * ib;
            vp += V4STRIDE;
            *vp = make_float4(si, sp, spi, sii);
        }
    }
    __syncthreads();

    // -------- Phase 2: horizontal sliding sums + guided-filter math ------
    // Minimum-tap version: 17 warmup loads (first 13 kept in a register
    // ring as the future "leaving" taps) + 13 entering-tap loads = 30
    // float4 LDS per 14-pixel segment (information-theoretic minimum).
    {
        const int row = tid & (OY - 1);   // 0..31
        const int seg = tid >> 5;         // 0..7
        const int xs = seg * SEGW;
        const float4* vrow = VS + row * V4STRIDE;
        float* itrow = IT + row * ITSTRIDE;

        float4 lv[SEGW - 1];              // leaving taps xs..xs+12
        float h0 = 0.f, h1 = 0.f, h2 = 0.f, h3 = 0.f;
        #pragma unroll
        for (int d = 0; d < 2 * R + 1; ++d) {
            float4 t = vrow[xs + d];
            if (d < SEGW - 1) lv[d] = t;
            h0 += t.x; h1 += t.y; h2 += t.z; h3 += t.w;
        }

        if (interior) {
            const float invN = 1.0f / ((2 * R + 1) * (2 * R + 1));
            #pragma unroll
            for (int j = 0; j < SEGW; ++j) {
                int xo = xs + j;
                float mi  = h0 * invN;
                float mp  = h1 * invN;
                float mpi = h2 * invN;
                float mii = h3 * invN;
                float cov_ip = mpi - mp * mi;
                float cov_ii = mii - mi * mi;
                float a = __fdividef(cov_ip, cov_ii + EPSF);
                float b = mp - a * mi;
                float iv = itrow[xo];
                float q = fminf(fmaxf(a * iv + b, 0.f), 1.f);
                itrow[xo] = q;
                if (j < SEGW - 1) {
                    float4 ta = vrow[xo + 2 * R + 1];   // entering tap
                    float4 tb = lv[j];                  // leaving tap (reg)
                    h0 += ta.x - tb.x;
                    h1 += ta.y - tb.y;
                    h2 += ta.z - tb.z;
                    h3 += ta.w - tb.w;
                }
            }
        } else {
            const int yg = y0 + row;
            int yl = yg - R; if (yl < 0) yl = 0;
            int yh = yg + R; if (yh > HH - 1) yh = HH - 1;
            const float ny = (float)(yh - yl + 1);
            #pragma unroll
            for (int j = 0; j < SEGW; ++j) {
                int xo = xs + j;
                int xg = x0 + xo;
                if (xg < WW) {
                    int xl = xg - R; if (xl < 0) xl = 0;
                    int xh = xg + R; if (xh > WW - 1) xh = WW - 1;
                    float nx = (float)(xh - xl + 1);
                    float invN = __fdividef(1.0f, ny * nx);
                    float mi  = h0 * invN;
                    float mp  = h1 * invN;
                    float mpi = h2 * invN;
                    float mii = h3 * invN;
                    float cov_ip = mpi - mp * mi;
                    float cov_ii = mii - mi * mi;
                    float a = __fdividef(cov_ip, cov_ii + EPSF);
                    float b = mp - a * mi;
                    float iv = itrow[xo];
                    float q = fminf(fmaxf(a * iv + b, 0.f), 1.f);
                    itrow[xo] = q;
                }
                if (j < SEGW - 1) {
                    float4 ta = vrow[xo + 2 * R + 1];
                    float4 tb = lv[j];
                    h0 += ta.x - tb.x;
                    h1 += ta.y - tb.y;
                    h2 += ta.z - tb.z;
                    h3 += ta.w - tb.w;
                }
            }
        }
    }
    __syncthreads();

    // ---------------- Phase 3: coalesced store of q ----------------------
    {
        float* Qb = Q + base + (size_t)y0 * WW + x0;
        int row = tid / OX;
        int xo  = tid - row * OX;
        if (x0 + OX <= WW) {
            #pragma unroll
            for (int it = 0; it < (OY * OX) / NT; ++it) {   // 14 iters, exact
                Qb[(size_t)row * WW + xo] = IT[row * ITSTRIDE + xo];
                xo += NT - 2 * OX;     // 256 = 2*112 + 32
                row += 2;
                if (xo >= OX) { xo -= OX; row += 1; }
            }
        } else {
            #pragma unroll
            for (int it = 0; it < (OY * OX) / NT; ++it) {
                if (x0 + xo < WW)
                    Qb[(size_t)row * WW + xo] = IT[row * ITSTRIDE + xo];
                xo += NT - 2 * OX;
                row += 2;
                if (xo >= OX) { xo -= OX; row += 1; }
            }
        }
    }
}

extern "C" void kernel_launch(void* const* d_in, const int* in_sizes, int n_in,
                              void* d_out, int out_size)
{
    const float* I = (const float*)d_in[0];
    const float* P = (const float*)d_in[1];
    float* Q = (float*)d_out;

    cudaFuncSetAttribute(gf_kernel,
                         cudaFuncAttributeMaxDynamicSharedMemorySize,
                         SMEM_BYTES);

    dim3 grid((WW + OX - 1) / OX, HH / OY, CC);
    gf_kernel<<<grid, NT, SMEM_BYTES>>>(I, P, Q);
}